// round 4
// baseline (speedup 1.0000x reference)
#include <cuda_runtime.h>
#include <cuda_bf16.h>
#include <math.h>

// Problem constants
#define N_B   2
#define L_S   1024
#define D_M   4544
#define H_Q   71
#define DKV   64
#define NL    (N_B * L_S)          // 2048
#define QKV_N (D_M + 2 * DKV)      // 4672

typedef unsigned long long ull;

// ---------------------------------------------------------------------------
// packed f32x2 helpers (sm_100+ PTX; doubles fp32 FMA throughput vs FFMA-3reg)
// ---------------------------------------------------------------------------
__device__ __forceinline__ ull ffma2(ull a, ull b, ull c) {
    ull d;
    asm("fma.rn.f32x2 %0, %1, %2, %3;" : "=l"(d) : "l"(a), "l"(b), "l"(c));
    return d;
}
__device__ __forceinline__ ull fmul2(ull a, ull b) {
    ull d;
    asm("mul.rn.f32x2 %0, %1, %2;" : "=l"(d) : "l"(a), "l"(b));
    return d;
}
__device__ __forceinline__ ull fpack2(float lo, float hi) {
    ull d;
    asm("mov.b64 %0, {%1, %2};" : "=l"(d) : "f"(lo), "f"(hi));
    return d;
}
__device__ __forceinline__ float2 funpack2(ull v) {
    float2 r;
    asm("mov.b64 {%0, %1}, %2;" : "=f"(r.x), "=f"(r.y) : "l"(v));
    return r;
}

// ---------------------------------------------------------------------------
// Scratch (no allocation allowed -> __device__ globals)
// ---------------------------------------------------------------------------
__device__ float g_fused[(size_t)NL * QKV_N];             // QKV projection out
__device__ float g_q[(size_t)N_B * H_Q * L_S * DKV];      // RoPE'd Q  [n,h,l,d]
__device__ float g_k[(size_t)N_B * L_S * DKV];            // RoPE'd K  [n,l,d]
__device__ float g_v[(size_t)N_B * L_S * DKV];            // V         [n,l,d]
__device__ float g_attn[(size_t)NL * D_M];                // attention out [n,l,h*d]

// ---------------------------------------------------------------------------
// SGEMM (NT): C[m][n] = sum_k A[m][k] * B[n][k]
// BM=128, BN=128, BK=16, 256 threads, 8x8 per thread (M-pairs packed in f32x2)
// Requires: M % 128 == 0, K % 16 == 0. N guarded.
// ---------------------------------------------------------------------------
#define GBM 128
#define GBN 128
#define GBK 16

__global__ __launch_bounds__(256, 2)
void sgemm_nt(const float* __restrict__ A, const float* __restrict__ B,
              float* __restrict__ C, int M, int Nn, int K) {
    __shared__ float As[GBK][GBM];
    __shared__ float Bs[GBK][GBN];

    const int tid = threadIdx.x;
    const int m0  = blockIdx.y * GBM;
    const int n0  = blockIdx.x * GBN;
    const int tx  = tid & 15;   // n direction (8 cols each)
    const int ty  = tid >> 4;   // m direction (8 rows each)

    ull acc[4][8];
#pragma unroll
    for (int i = 0; i < 4; i++)
#pragma unroll
        for (int j = 0; j < 8; j++) acc[i][j] = 0ull;

    for (int k0 = 0; k0 < K; k0 += GBK) {
        // cooperative loads: 2 x float4 per thread per tile
#pragma unroll
        for (int p = 0; p < 2; p++) {
            const int lin = tid + p * 256;
            const int row = lin >> 2;          // 0..127
            const int kq  = (lin & 3) << 2;    // 0,4,8,12
            const float4 av = *(const float4*)(A + (size_t)(m0 + row) * K + k0 + kq);
            As[kq + 0][row] = av.x; As[kq + 1][row] = av.y;
            As[kq + 2][row] = av.z; As[kq + 3][row] = av.w;

            float4 bv = make_float4(0.f, 0.f, 0.f, 0.f);
            const int bn = n0 + row;
            if (bn < Nn) bv = *(const float4*)(B + (size_t)bn * K + k0 + kq);
            Bs[kq + 0][row] = bv.x; Bs[kq + 1][row] = bv.y;
            Bs[kq + 2][row] = bv.z; Bs[kq + 3][row] = bv.w;
        }
        __syncthreads();

#pragma unroll
        for (int kk = 0; kk < GBK; kk++) {
            const ull* ap = (const ull*)&As[kk][ty * 8];   // 4 M-pairs, pre-packed
            ull a2[4];
#pragma unroll
            for (int i = 0; i < 4; i++) a2[i] = ap[i];
            ull b2[8];
#pragma unroll
            for (int j = 0; j < 8; j++) {
                const float bv = Bs[kk][tx * 8 + j];
                b2[j] = fpack2(bv, bv);
            }
#pragma unroll
            for (int i = 0; i < 4; i++)
#pragma unroll
                for (int j = 0; j < 8; j++)
                    acc[i][j] = ffma2(a2[i], b2[j], acc[i][j]);
        }
        __syncthreads();
    }

#pragma unroll
    for (int i = 0; i < 4; i++) {
        const int m = m0 + ty * 8 + i * 2;
#pragma unroll
        for (int j = 0; j < 8; j++) {
            const int n = n0 + tx * 8 + j;
            if (n < Nn) {
                const float2 v = funpack2(acc[i][j]);
                C[(size_t)m * Nn + n]       = v.x;
                C[(size_t)(m + 1) * Nn + n] = v.y;
            }
        }
    }
}

// ---------------------------------------------------------------------------
// RoPE + scatter:  fused[n,l,73,64] -> q[n,h,l,d] (roped), k[n,l,d] (roped),
//                  v[n,l,d] (copy). One block per (n,l).
// ---------------------------------------------------------------------------
__global__ void rope_kernel(const float* __restrict__ fused,
                            float* __restrict__ q, float* __restrict__ k,
                            float* __restrict__ v) {
    const int nl = blockIdx.x;
    const int n  = nl >> 10;
    const int l  = nl & (L_S - 1);
    __shared__ float cs[32], sn[32];
    const int tid = threadIdx.x;
    if (tid < 32) {
        const double f   = pow(10000.0, -(double)tid / 32.0);
        const double ang = (double)l * f;
        cs[tid] = (float)cos(ang);
        sn[tid] = (float)sin(ang);
    }
    __syncthreads();

    const float* src = fused + (size_t)nl * QKV_N;
    for (int idx = tid; idx < (H_Q + 2) * DKV; idx += blockDim.x) {
        const int head = idx >> 6;
        const int d    = idx & 63;
        const float x  = src[idx];
        float out = x;
        if (head < H_Q + 1) {  // rope on q heads and k head
            const int i = d & 31;
            const float c = cs[i], s = sn[i];
            if (d < 32) out = x * c - src[idx + 32] * s;
            else        out = x * c + src[idx - 32] * s;
        }
        if (head < H_Q)
            q[(((size_t)n * H_Q + head) * L_S + l) * DKV + d] = out;
        else if (head == H_Q)
            k[((size_t)n * L_S + l) * DKV + d] = out;
        else
            v[((size_t)n * L_S + l) * DKV + d] = x;
    }
}

// ---------------------------------------------------------------------------
// Causal MQA flash attention (fp32, f32x2 math).
// grid = (L/128, H, N), block = 128 threads, 1 thread = 1 query row.
// K/V tiles of 64 rows in smem; all smem reads are warp-broadcast (row j is
// the loop index, identical across lanes) -> conflict-free.
// ---------------------------------------------------------------------------
__global__ __launch_bounds__(128, 3)
void attn_kernel(const float* __restrict__ Q, const float* __restrict__ Kb,
                 const float* __restrict__ Vb, float* __restrict__ O) {
    __shared__ float Ks[64][64];
    __shared__ float Vs[64][64];

    const int qt  = (int)gridDim.x - 1 - (int)blockIdx.x;  // heavy tiles first
    const int h   = blockIdx.y;
    const int n   = blockIdx.z;
    const int tid = threadIdx.x;
    const int qi  = qt * 128 + tid;

    const float* qrow = Q + (((size_t)n * H_Q + h) * L_S + qi) * DKV;
    ull q2[32];
    {
        const ulonglong2* qp = (const ulonglong2*)qrow;
#pragma unroll
        for (int t = 0; t < 16; t++) {
            const ulonglong2 w = qp[t];
            q2[2 * t] = w.x; q2[2 * t + 1] = w.y;
        }
    }
    ull o2[32];
#pragma unroll
    for (int d = 0; d < 32; d++) o2[d] = 0ull;
    float mrow = -1e30f, lsum = 0.f;

    const float* Kbase = Kb + (size_t)n * L_S * DKV;
    const float* Vbase = Vb + (size_t)n * L_S * DKV;
    const int ktend = 2 * qt + 1;

    for (int kt = 0; kt <= ktend; kt++) {
        __syncthreads();
#pragma unroll
        for (int p = 0; p < 8; p++) {
            const int lin = tid + p * 128;      // float4 index within 64x64 tile
            const int r = lin >> 4;
            const int c = (lin & 15) << 2;
            ((float4*)Ks)[lin] = *(const float4*)(Kbase + ((size_t)kt * 64 + r) * DKV + c);
            ((float4*)Vs)[lin] = *(const float4*)(Vbase + ((size_t)kt * 64 + r) * DKV + c);
        }
        __syncthreads();

        const int kbase = kt * 64;
        for (int jc = 0; jc < 8; jc++) {        // chunks of 8 keys
            float sv[8];
            float cmax = -1e30f;
#pragma unroll
            for (int jj = 0; jj < 8; jj++) {
                const int j = jc * 8 + jj;
                const ulonglong2* krow = (const ulonglong2*)&Ks[j][0];
                ull accA = 0ull, accB = 0ull;
#pragma unroll
                for (int t = 0; t < 16; t++) {
                    const ulonglong2 kk = krow[t];
                    accA = ffma2(q2[2 * t],     kk.x, accA);
                    accB = ffma2(q2[2 * t + 1], kk.y, accB);
                }
                const float2 ra = funpack2(accA);
                const float2 rb = funpack2(accB);
                float s = (ra.x + ra.y + rb.x + rb.y) * 0.125f;
                if (kbase + j > qi) s = -1e30f;   // causal mask
                sv[jj] = s;
                cmax = fmaxf(cmax, s);
            }
            const float newm = fmaxf(mrow, cmax);
            const float corr = __expf(mrow - newm);
            const ull corr2 = fpack2(corr, corr);
#pragma unroll
            for (int d = 0; d < 32; d++) o2[d] = fmul2(o2[d], corr2);
            lsum *= corr;
#pragma unroll
            for (int jj = 0; jj < 8; jj++) {
                const float p = __expf(sv[jj] - newm);
                lsum += p;
                const ull p2 = fpack2(p, p);
                const ulonglong2* vrow = (const ulonglong2*)&Vs[jc * 8 + jj][0];
#pragma unroll
                for (int t = 0; t < 16; t++) {
                    const ulonglong2 vv = vrow[t];
                    o2[2 * t]     = ffma2(vv.x, p2, o2[2 * t]);
                    o2[2 * t + 1] = ffma2(vv.y, p2, o2[2 * t + 1]);
                }
            }
            mrow = newm;
        }
    }

    const float inv = 1.f / lsum;
    const ull inv2 = fpack2(inv, inv);
    float* orow = O + (((size_t)n * L_S + qi) * H_Q + h) * DKV;
#pragma unroll
    for (int d = 0; d < 32; d++) ((ull*)orow)[d] = fmul2(o2[d], inv2);
}

// ---------------------------------------------------------------------------
// launch
// ---------------------------------------------------------------------------
extern "C" void kernel_launch(void* const* d_in, const int* in_sizes, int n_in,
                              void* d_out, int out_size) {
    const float* hidden  = (const float*)d_in[0];  // [2,1024,4544]
    const float* w_qkv   = (const float*)d_in[1];  // [4672,4544]
    const float* w_dense = (const float*)d_in[2];  // [4544,4544]
    float* out = (float*)d_out;                    // [2,1024,4544]

    float *fused, *q, *k, *v, *attn;
    cudaGetSymbolAddress((void**)&fused, g_fused);
    cudaGetSymbolAddress((void**)&q,     g_q);
    cudaGetSymbolAddress((void**)&k,     g_k);
    cudaGetSymbolAddress((void**)&v,     g_v);
    cudaGetSymbolAddress((void**)&attn,  g_attn);

    {   // QKV projection: [2048,4544] x [4672,4544]^T
        dim3 grid((QKV_N + GBN - 1) / GBN, NL / GBM);
        sgemm_nt<<<grid, 256>>>(hidden, w_qkv, fused, NL, QKV_N, D_M);
    }
    rope_kernel<<<NL, 256>>>(fused, q, k, v);
    attn_kernel<<<dim3(L_S / 128, H_Q, N_B), 128>>>(q, k, v, attn);
    {   // dense projection: [2048,4544] x [4544,4544]^T
        dim3 grid((D_M + GBN - 1) / GBN, NL / GBM);
        sgemm_nt<<<grid, 256>>>(attn, w_dense, out, NL, D_M, D_M);
    }
}

// round 11
// speedup vs baseline: 1.8440x; 1.8440x over previous
#include <cuda_runtime.h>
#include <cuda_bf16.h>
#include <math.h>
#include <stdint.h>

// Problem constants
#define N_B   2
#define L_S   1024
#define D_M   4544
#define H_Q   71
#define DKV   64
#define NL    (N_B * L_S)          // 2048
#define QKV_N (D_M + 2 * DKV)      // 4672
#define QKV_NPAD 4736              // 37 * 128
#define DM_NPAD  4608              // 36 * 128

typedef unsigned long long ull;

// ---------------------------------------------------------------------------
// packed f32x2 helpers (attention kernel)
// ---------------------------------------------------------------------------
__device__ __forceinline__ ull ffma2(ull a, ull b, ull c) {
    ull d;
    asm("fma.rn.f32x2 %0, %1, %2, %3;" : "=l"(d) : "l"(a), "l"(b), "l"(c));
    return d;
}
__device__ __forceinline__ ull fmul2(ull a, ull b) {
    ull d;
    asm("mul.rn.f32x2 %0, %1, %2;" : "=l"(d) : "l"(a), "l"(b));
    return d;
}
__device__ __forceinline__ ull fpack2(float lo, float hi) {
    ull d;
    asm("mov.b64 %0, {%1, %2};" : "=l"(d) : "f"(lo), "f"(hi));
    return d;
}
__device__ __forceinline__ float2 funpack2(ull v) {
    float2 r;
    asm("mov.b64 {%0, %1}, %2;" : "=f"(r.x), "=f"(r.y) : "l"(v));
    return r;
}

// ---------------------------------------------------------------------------
// mma.sync / ldmatrix / cp.async helpers (portable sm_80+ ISA, works on sm_103)
// ---------------------------------------------------------------------------
__device__ __forceinline__ uint32_t smem_u32(const void* p) {
    uint32_t a;
    asm("{ .reg .u64 t; cvta.to.shared.u64 t, %1; cvt.u32.u64 %0, t; }" : "=r"(a) : "l"(p));
    return a;
}
__device__ __forceinline__ void cp16(uint32_t dst, const void* src) {
    asm volatile("cp.async.cg.shared.global [%0], [%1], 16;" :: "r"(dst), "l"(src) : "memory");
}
#define CP_COMMIT() asm volatile("cp.async.commit_group;" ::: "memory")
#define CP_WAIT(n)  asm volatile("cp.async.wait_group %0;" :: "n"(n) : "memory")

#define LDSM4(r, addr) \
    asm volatile("ldmatrix.sync.aligned.m8n8.x4.shared.b16 {%0,%1,%2,%3}, [%4];" \
        : "=r"((r)[0]), "=r"((r)[1]), "=r"((r)[2]), "=r"((r)[3]) : "r"(addr))

#define MMA_BF16(c, a, b0, b1) \
    asm volatile("mma.sync.aligned.m16n8k16.row.col.f32.bf16.bf16.f32 " \
        "{%0,%1,%2,%3}, {%4,%5,%6,%7}, {%8,%9}, {%0,%1,%2,%3};" \
        : "+f"((c)[0]), "+f"((c)[1]), "+f"((c)[2]), "+f"((c)[3]) \
        : "r"((a)[0]), "r"((a)[1]), "r"((a)[2]), "r"((a)[3]), "r"(b0), "r"(b1))

// ---------------------------------------------------------------------------
// Scratch (no allocation allowed -> __device__ globals)
// ---------------------------------------------------------------------------
__device__ float g_fused[(size_t)NL * QKV_N];
__device__ float g_q[(size_t)N_B * H_Q * L_S * DKV];
__device__ float g_k[(size_t)N_B * L_S * DKV];
__device__ float g_v[(size_t)N_B * L_S * DKV];
__device__ float g_attn[(size_t)NL * D_M];
// bf16 hi/lo split operands (weights padded with zero rows to a tile multiple)
__device__ __nv_bfloat16 g_hid_h[(size_t)NL * D_M];
__device__ __nv_bfloat16 g_hid_l[(size_t)NL * D_M];
__device__ __nv_bfloat16 g_wq_h[(size_t)QKV_NPAD * D_M];
__device__ __nv_bfloat16 g_wq_l[(size_t)QKV_NPAD * D_M];
__device__ __nv_bfloat16 g_wd_h[(size_t)DM_NPAD * D_M];
__device__ __nv_bfloat16 g_wd_l[(size_t)DM_NPAD * D_M];
__device__ __nv_bfloat16 g_at_h[(size_t)NL * D_M];
__device__ __nv_bfloat16 g_at_l[(size_t)NL * D_M];

// ---------------------------------------------------------------------------
// f32 -> (bf16 hi, bf16 lo) split with zero padding past nvalid.
// ---------------------------------------------------------------------------
__global__ void split_bf16(const float* __restrict__ src, __nv_bfloat16* __restrict__ hi,
                           __nv_bfloat16* __restrict__ lo, long nvalid, long ntotal) {
    const long i4 = ((long)blockIdx.x * blockDim.x + threadIdx.x) * 4;
    if (i4 >= ntotal) return;
    float x[4] = {0.f, 0.f, 0.f, 0.f};
    if (i4 < nvalid) {
        const float4 v = *(const float4*)(src + i4);
        x[0] = v.x; x[1] = v.y; x[2] = v.z; x[3] = v.w;
    }
    __nv_bfloat16 h[4], l[4];
#pragma unroll
    for (int e = 0; e < 4; e++) {
        h[e] = __float2bfloat16(x[e]);
        l[e] = __float2bfloat16(x[e] - __bfloat162float(h[e]));
    }
    __nv_bfloat162* hp = (__nv_bfloat162*)(hi + i4);
    __nv_bfloat162* lp = (__nv_bfloat162*)(lo + i4);
    hp[0] = __nv_bfloat162(h[0], h[1]); hp[1] = __nv_bfloat162(h[2], h[3]);
    lp[0] = __nv_bfloat162(l[0], l[1]); lp[1] = __nv_bfloat162(l[2], l[3]);
}

// ---------------------------------------------------------------------------
// mma.sync bf16 3-pass split GEMM (NT): C[m][n] = sum_k A[m][k]*B[n][k], f32 acc.
// 128x128 CTA tile, BK=32, 256 threads (8 warps of 32x64), cp.async double buffer.
// Smem rows padded 64B->80B (stride 5*16B, coprime 8 banks => conflict-free).
// ---------------------------------------------------------------------------
#define RS      40                 // bf16 elements per smem row (32 data + 8 pad)
#define RSB     80                 // bytes per smem row
#define TILE_B  (128 * RSB)        // 10240 B per operand tile
#define STAGE_B (4 * TILE_B)       // Ah, Al, Bh, Bl
#define GSMEM   (2 * STAGE_B)      // 81920 B

__device__ __forceinline__ void issue_stage(
    uint32_t stage, const __nv_bfloat16* Ah, const __nv_bfloat16* Al,
    const __nv_bfloat16* Bh, const __nv_bfloat16* Bl,
    int m0, int n0, int kk, int K, int tid) {
#pragma unroll
    for (int a = 0; a < 4; a++) {
        const __nv_bfloat16* g = (a == 0) ? Ah : (a == 1) ? Al : (a == 2) ? Bh : Bl;
        const int r0 = (a < 2) ? m0 : n0;
#pragma unroll
        for (int j = 0; j < 2; j++) {
            const int lin = tid + j * 256;
            const int row = lin >> 2;
            const int q   = lin & 3;
            cp16(stage + a * TILE_B + row * RSB + q * 16,
                 g + (size_t)(r0 + row) * K + kk + q * 8);
        }
    }
    CP_COMMIT();
}

__global__ void __launch_bounds__(256, 1)
gemm_mma3(const __nv_bfloat16* __restrict__ Ah, const __nv_bfloat16* __restrict__ Al,
          const __nv_bfloat16* __restrict__ Bh, const __nv_bfloat16* __restrict__ Bl,
          float* __restrict__ C, int Nn, int K) {
    extern __shared__ char dsm[];
    const uint32_t sb = smem_u32(dsm);
    const int tid  = threadIdx.x;
    const int lane = tid & 31;
    const int wid  = tid >> 5;
    const int wm   = wid & 3;        // 4 warps along M (32 rows each)
    const int wn   = wid >> 2;       // 2 warps along N (64 cols each)
    const int m0   = blockIdx.y * 128;
    const int n0   = blockIdx.x * 128;

    float acc[2][8][4];
#pragma unroll
    for (int mt = 0; mt < 2; mt++)
#pragma unroll
        for (int nt = 0; nt < 8; nt++)
#pragma unroll
            for (int e = 0; e < 4; e++) acc[mt][nt][e] = 0.f;

    const int nkt = K / 32;          // 142
    issue_stage(sb, Ah, Al, Bh, Bl, m0, n0, 0, K, tid);

    for (int kt = 0; kt < nkt; kt++) {
        const uint32_t stage = sb + (kt & 1) * STAGE_B;
        if (kt + 1 < nkt) {
            issue_stage(sb + ((kt + 1) & 1) * STAGE_B, Ah, Al, Bh, Bl,
                        m0, n0, (kt + 1) * 32, K, tid);
            CP_WAIT(1);
        } else {
            CP_WAIT(0);
        }
        __syncthreads();

#pragma unroll
        for (int k16 = 0; k16 < 2; k16++) {
            const uint32_t koff = k16 * 32;   // 16 bf16 = 32 bytes
            uint32_t ah[2][4], al[2][4];
#pragma unroll
            for (int mt = 0; mt < 2; mt++) {
                const uint32_t ra = stage +
                    (uint32_t)((wm * 32 + mt * 16 + (lane & 15)) * RSB + (lane >> 4) * 16) + koff;
                LDSM4(ah[mt], ra);
                LDSM4(al[mt], ra + TILE_B);
            }
            uint32_t bh[4][4], bl[4][4];
#pragma unroll
            for (int p = 0; p < 4; p++) {
                const uint32_t rb = stage + 2 * TILE_B +
                    (uint32_t)((wn * 64 + p * 16 + (lane & 15)) * RSB + (lane >> 4) * 16) + koff;
                LDSM4(bh[p], rb);
                LDSM4(bl[p], rb + TILE_B);
            }
#pragma unroll
            for (int mt = 0; mt < 2; mt++)
#pragma unroll
                for (int nt = 0; nt < 8; nt++) {
                    const int p = nt >> 1, s = nt & 1;
                    MMA_BF16(acc[mt][nt], ah[mt], bh[p][s], bh[p][2 + s]);
                    MMA_BF16(acc[mt][nt], ah[mt], bl[p][s], bl[p][2 + s]);
                    MMA_BF16(acc[mt][nt], al[mt], bh[p][s], bh[p][2 + s]);
                }
        }
        __syncthreads();
    }

    // Epilogue: direct fragment stores (float2, 8B aligned since cols are even)
#pragma unroll
    for (int mt = 0; mt < 2; mt++) {
        const int row0 = m0 + wm * 32 + mt * 16 + (lane >> 2);
#pragma unroll
        for (int nt = 0; nt < 8; nt++) {
            const int col = n0 + wn * 64 + nt * 8 + (lane & 3) * 2;
            if (col < Nn) {
                float2 v01; v01.x = acc[mt][nt][0]; v01.y = acc[mt][nt][1];
                float2 v23; v23.x = acc[mt][nt][2]; v23.y = acc[mt][nt][3];
                *(float2*)(C + (size_t)row0 * Nn + col)       = v01;
                *(float2*)(C + (size_t)(row0 + 8) * Nn + col) = v23;
            }
        }
    }
}

// ---------------------------------------------------------------------------
// RoPE + scatter (unchanged)
// ---------------------------------------------------------------------------
__global__ void rope_kernel(const float* __restrict__ fused,
                            float* __restrict__ q, float* __restrict__ k,
                            float* __restrict__ v) {
    const int nl = blockIdx.x;
    const int n  = nl >> 10;
    const int l  = nl & (L_S - 1);
    __shared__ float cs[32], sn[32];
    const int tid = threadIdx.x;
    if (tid < 32) {
        const double f   = pow(10000.0, -(double)tid / 32.0);
        const double ang = (double)l * f;
        cs[tid] = (float)cos(ang);
        sn[tid] = (float)sin(ang);
    }
    __syncthreads();

    const float* src = fused + (size_t)nl * QKV_N;
    for (int idx = tid; idx < (H_Q + 2) * DKV; idx += blockDim.x) {
        const int head = idx >> 6;
        const int d    = idx & 63;
        const float x  = src[idx];
        float out = x;
        if (head < H_Q + 1) {
            const int i = d & 31;
            const float c = cs[i], s = sn[i];
            if (d < 32) out = x * c - src[idx + 32] * s;
            else        out = x * c + src[idx - 32] * s;
        }
        if (head < H_Q)
            q[(((size_t)n * H_Q + head) * L_S + l) * DKV + d] = out;
        else if (head == H_Q)
            k[((size_t)n * L_S + l) * DKV + d] = out;
        else
            v[((size_t)n * L_S + l) * DKV + d] = x;
    }
}

// ---------------------------------------------------------------------------
// Causal MQA flash attention (unchanged, f32x2 math)
// ---------------------------------------------------------------------------
__global__ __launch_bounds__(128, 3)
void attn_kernel(const float* __restrict__ Q, const float* __restrict__ Kb,
                 const float* __restrict__ Vb, float* __restrict__ O) {
    __shared__ float Ks[64][64];
    __shared__ float Vs[64][64];

    const int qt  = (int)gridDim.x - 1 - (int)blockIdx.x;
    const int h   = blockIdx.y;
    const int n   = blockIdx.z;
    const int tid = threadIdx.x;
    const int qi  = qt * 128 + tid;

    const float* qrow = Q + (((size_t)n * H_Q + h) * L_S + qi) * DKV;
    ull q2[32];
    {
        const ulonglong2* qp = (const ulonglong2*)qrow;
#pragma unroll
        for (int t = 0; t < 16; t++) {
            const ulonglong2 w = qp[t];
            q2[2 * t] = w.x; q2[2 * t + 1] = w.y;
        }
    }
    ull o2[32];
#pragma unroll
    for (int d = 0; d < 32; d++) o2[d] = 0ull;
    float mrow = -1e30f, lsum = 0.f;

    const float* Kbase = Kb + (size_t)n * L_S * DKV;
    const float* Vbase = Vb + (size_t)n * L_S * DKV;
    const int ktend = 2 * qt + 1;

    for (int kt = 0; kt <= ktend; kt++) {
        __syncthreads();
#pragma unroll
        for (int p = 0; p < 8; p++) {
            const int lin = tid + p * 128;
            const int r = lin >> 4;
            const int c = (lin & 15) << 2;
            ((float4*)Ks)[lin] = *(const float4*)(Kbase + ((size_t)kt * 64 + r) * DKV + c);
            ((float4*)Vs)[lin] = *(const float4*)(Vbase + ((size_t)kt * 64 + r) * DKV + c);
        }
        __syncthreads();

        const int kbase = kt * 64;
        for (int jc = 0; jc < 8; jc++) {
            float sv[8];
            float cmax = -1e30f;
#pragma unroll
            for (int jj = 0; jj < 8; jj++) {
                const int j = jc * 8 + jj;
                const ulonglong2* krow = (const ulonglong2*)&Ks[j][0];
                ull accA = 0ull, accB = 0ull;
#pragma unroll
                for (int t = 0; t < 16; t++) {
                    const ulonglong2 kk = krow[t];
                    accA = ffma2(q2[2 * t],     kk.x, accA);
                    accB = ffma2(q2[2 * t + 1], kk.y, accB);
                }
                const float2 ra = funpack2(accA);
                const float2 rb = funpack2(accB);
                float s = (ra.x + ra.y + rb.x + rb.y) * 0.125f;
                if (kbase + j > qi) s = -1e30f;
                sv[jj] = s;
                cmax = fmaxf(cmax, s);
            }
            const float newm = fmaxf(mrow, cmax);
            const float corr = __expf(mrow - newm);
            const ull corr2 = fpack2(corr, corr);
#pragma unroll
            for (int d = 0; d < 32; d++) o2[d] = fmul2(o2[d], corr2);
            lsum *= corr;
#pragma unroll
            for (int jj = 0; jj < 8; jj++) {
                const float p = __expf(sv[jj] - newm);
                lsum += p;
                const ull p2 = fpack2(p, p);
                const ulonglong2* vrow = (const ulonglong2*)&Vs[jc * 8 + jj][0];
#pragma unroll
                for (int t = 0; t < 16; t++) {
                    const ulonglong2 vv = vrow[t];
                    o2[2 * t]     = ffma2(vv.x, p2, o2[2 * t]);
                    o2[2 * t + 1] = ffma2(vv.y, p2, o2[2 * t + 1]);
                }
            }
            mrow = newm;
        }
    }

    const float inv = 1.f / lsum;
    const ull inv2 = fpack2(inv, inv);
    float* orow = O + (((size_t)n * L_S + qi) * H_Q + h) * DKV;
#pragma unroll
    for (int d = 0; d < 32; d++) ((ull*)orow)[d] = fmul2(o2[d], inv2);
}

// ---------------------------------------------------------------------------
// launch
// ---------------------------------------------------------------------------
static inline int grid4(long ntotal) { return (int)((ntotal / 4 + 255) / 256); }

extern "C" void kernel_launch(void* const* d_in, const int* in_sizes, int n_in,
                              void* d_out, int out_size) {
    const float* hidden  = (const float*)d_in[0];  // [2,1024,4544]
    const float* w_qkv   = (const float*)d_in[1];  // [4672,4544]
    const float* w_dense = (const float*)d_in[2];  // [4544,4544]
    float* out = (float*)d_out;                    // [2,1024,4544]

    float *fused, *q, *k, *v, *attn;
    __nv_bfloat16 *hid_h, *hid_l, *wq_h, *wq_l, *wd_h, *wd_l, *at_h, *at_l;
    cudaGetSymbolAddress((void**)&fused, g_fused);
    cudaGetSymbolAddress((void**)&q,     g_q);
    cudaGetSymbolAddress((void**)&k,     g_k);
    cudaGetSymbolAddress((void**)&v,     g_v);
    cudaGetSymbolAddress((void**)&attn,  g_attn);
    cudaGetSymbolAddress((void**)&hid_h, g_hid_h);
    cudaGetSymbolAddress((void**)&hid_l, g_hid_l);
    cudaGetSymbolAddress((void**)&wq_h,  g_wq_h);
    cudaGetSymbolAddress((void**)&wq_l,  g_wq_l);
    cudaGetSymbolAddress((void**)&wd_h,  g_wd_h);
    cudaGetSymbolAddress((void**)&wd_l,  g_wd_l);
    cudaGetSymbolAddress((void**)&at_h,  g_at_h);
    cudaGetSymbolAddress((void**)&at_l,  g_at_l);

    cudaFuncSetAttribute(gemm_mma3, cudaFuncAttributeMaxDynamicSharedMemorySize, GSMEM);

    const long n_hid = (long)NL * D_M;
    const long n_wq  = (long)QKV_N * D_M;
    const long n_wqp = (long)QKV_NPAD * D_M;
    const long n_wd  = (long)D_M * D_M;
    const long n_wdp = (long)DM_NPAD * D_M;

    split_bf16<<<grid4(n_hid), 256>>>(hidden,  hid_h, hid_l, n_hid, n_hid);
    split_bf16<<<grid4(n_wqp), 256>>>(w_qkv,   wq_h,  wq_l,  n_wq,  n_wqp);
    split_bf16<<<grid4(n_wdp), 256>>>(w_dense, wd_h,  wd_l,  n_wd,  n_wdp);

    // QKV projection: [2048,4544] x [4672,4544]^T -> fused
    gemm_mma3<<<dim3(QKV_NPAD / 128, NL / 128), 256, GSMEM>>>(
        hid_h, hid_l, wq_h, wq_l, fused, QKV_N, D_M);

    rope_kernel<<<NL, 256>>>(fused, q, k, v);
    attn_kernel<<<dim3(L_S / 128, H_Q, N_B), 128>>>(q, k, v, attn);

    split_bf16<<<grid4(n_hid), 256>>>(attn, at_h, at_l, n_hid, n_hid);

    // Dense projection: [2048,4544] x [4544,4544]^T -> out
    gemm_mma3<<<dim3(DM_NPAD / 128, NL / 128), 256, GSMEM>>>(
        at_h, at_l, wd_h, wd_l, out, D_M, D_M);
}

// round 15
// speedup vs baseline: 1.9415x; 1.0529x over previous
#include <cuda_runtime.h>
#include <cuda_bf16.h>
#include <math.h>
#include <stdint.h>

// Problem constants
#define N_B   2
#define L_S   1024
#define D_M   4544
#define H_Q   71
#define DKV   64
#define NL    (N_B * L_S)          // 2048
#define QKV_N (D_M + 2 * DKV)      // 4672
#define QKV_NPAD 4736              // 37 * 128
#define DM_NPAD  4608              // 36 * 128

typedef unsigned long long ull;

// ---------------------------------------------------------------------------
// packed f32x2 helpers (attention kernel)
// ---------------------------------------------------------------------------
__device__ __forceinline__ ull ffma2(ull a, ull b, ull c) {
    ull d;
    asm("fma.rn.f32x2 %0, %1, %2, %3;" : "=l"(d) : "l"(a), "l"(b), "l"(c));
    return d;
}
__device__ __forceinline__ ull fmul2(ull a, ull b) {
    ull d;
    asm("mul.rn.f32x2 %0, %1, %2;" : "=l"(d) : "l"(a), "l"(b));
    return d;
}
__device__ __forceinline__ ull fpack2(float lo, float hi) {
    ull d;
    asm("mov.b64 %0, {%1, %2};" : "=l"(d) : "f"(lo), "f"(hi));
    return d;
}
__device__ __forceinline__ float2 funpack2(ull v) {
    float2 r;
    asm("mov.b64 {%0, %1}, %2;" : "=f"(r.x), "=f"(r.y) : "l"(v));
    return r;
}

// ---------------------------------------------------------------------------
// mma.sync / ldmatrix / cp.async helpers (portable sm_80+ ISA, works on sm_103)
// ---------------------------------------------------------------------------
__device__ __forceinline__ uint32_t smem_u32(const void* p) {
    uint32_t a;
    asm("{ .reg .u64 t; cvta.to.shared.u64 t, %1; cvt.u32.u64 %0, t; }" : "=r"(a) : "l"(p));
    return a;
}
__device__ __forceinline__ void cp16(uint32_t dst, const void* src) {
    asm volatile("cp.async.cg.shared.global [%0], [%1], 16;" :: "r"(dst), "l"(src) : "memory");
}
#define CP_COMMIT() asm volatile("cp.async.commit_group;" ::: "memory")
#define CP_WAIT(n)  asm volatile("cp.async.wait_group %0;" :: "n"(n) : "memory")

#define LDSM4(r, addr) \
    asm volatile("ldmatrix.sync.aligned.m8n8.x4.shared.b16 {%0,%1,%2,%3}, [%4];" \
        : "=r"((r)[0]), "=r"((r)[1]), "=r"((r)[2]), "=r"((r)[3]) : "r"(addr))

#define MMA_BF16(c, a, b0, b1) \
    asm volatile("mma.sync.aligned.m16n8k16.row.col.f32.bf16.bf16.f32 " \
        "{%0,%1,%2,%3}, {%4,%5,%6,%7}, {%8,%9}, {%0,%1,%2,%3};" \
        : "+f"((c)[0]), "+f"((c)[1]), "+f"((c)[2]), "+f"((c)[3]) \
        : "r"((a)[0]), "r"((a)[1]), "r"((a)[2]), "r"((a)[3]), "r"(b0), "r"(b1))

// ---------------------------------------------------------------------------
// Scratch (no allocation allowed -> __device__ globals)
// ---------------------------------------------------------------------------
__device__ float g_fused[(size_t)NL * QKV_N];
__device__ float g_q[(size_t)N_B * H_Q * L_S * DKV];
__device__ float g_k[(size_t)N_B * L_S * DKV];
__device__ float g_v[(size_t)N_B * L_S * DKV];
__device__ float g_attn[(size_t)NL * D_M];
// bf16 hi/lo split operands (weights padded with zero rows to a tile multiple)
__device__ __nv_bfloat16 g_hid_h[(size_t)NL * D_M];
__device__ __nv_bfloat16 g_hid_l[(size_t)NL * D_M];
__device__ __nv_bfloat16 g_wq_h[(size_t)QKV_NPAD * D_M];
__device__ __nv_bfloat16 g_wq_l[(size_t)QKV_NPAD * D_M];
__device__ __nv_bfloat16 g_wd_h[(size_t)DM_NPAD * D_M];
__device__ __nv_bfloat16 g_wd_l[(size_t)DM_NPAD * D_M];
__device__ __nv_bfloat16 g_at_h[(size_t)NL * D_M];
__device__ __nv_bfloat16 g_at_l[(size_t)NL * D_M];

// ---------------------------------------------------------------------------
// f32 -> (bf16 hi, bf16 lo) split with zero padding past nvalid.
// ---------------------------------------------------------------------------
__global__ void split_bf16(const float* __restrict__ src, __nv_bfloat16* __restrict__ hi,
                           __nv_bfloat16* __restrict__ lo, long nvalid, long ntotal) {
    const long i4 = ((long)blockIdx.x * blockDim.x + threadIdx.x) * 4;
    if (i4 >= ntotal) return;
    float x[4] = {0.f, 0.f, 0.f, 0.f};
    if (i4 < nvalid) {
        const float4 v = *(const float4*)(src + i4);
        x[0] = v.x; x[1] = v.y; x[2] = v.z; x[3] = v.w;
    }
    __nv_bfloat16 h[4], l[4];
#pragma unroll
    for (int e = 0; e < 4; e++) {
        h[e] = __float2bfloat16(x[e]);
        l[e] = __float2bfloat16(x[e] - __bfloat162float(h[e]));
    }
    __nv_bfloat162* hp = (__nv_bfloat162*)(hi + i4);
    __nv_bfloat162* lp = (__nv_bfloat162*)(lo + i4);
    hp[0] = __nv_bfloat162(h[0], h[1]); hp[1] = __nv_bfloat162(h[2], h[3]);
    lp[0] = __nv_bfloat162(l[0], l[1]); lp[1] = __nv_bfloat162(l[2], l[3]);
}

// ---------------------------------------------------------------------------
// mma.sync bf16 3-pass split GEMM (NT): C[m][n] = sum_k A[m][k]*B[n][k], f32 acc.
// CTA tile 256(M)x128(N), BK=32, 512 threads (16 warps of 32x64),
// 3-stage cp.async pipeline. Smem rows 64B data + 16B pad => conflict-free.
// ---------------------------------------------------------------------------
#define RSB     80                 // bytes per smem row (64 data + 16 pad)
#define A_TILE  (256 * RSB)        // 20480 B (one of Ah / Al)
#define B_TILE  (128 * RSB)        // 10240 B (one of Bh / Bl)
#define STAGE_B (2 * A_TILE + 2 * B_TILE)   // 61440 B
#define GSMEM   (3 * STAGE_B)               // 184320 B

__device__ __forceinline__ void issue_stage(
    uint32_t stage, const __nv_bfloat16* Ah, const __nv_bfloat16* Al,
    const __nv_bfloat16* Bh, const __nv_bfloat16* Bl,
    int m0, int n0, int kk, int K, int tid) {
    // A: 2 tiles (hi/lo) x 256 rows x 4 chunks = 2048 cp ops
#pragma unroll
    for (int j = 0; j < 4; j++) {
        const int lin = tid + j * 512;
        const __nv_bfloat16* g = (lin < 1024) ? Ah : Al;
        const uint32_t base = stage + ((lin < 1024) ? 0u : (uint32_t)A_TILE);
        const int r = (lin & 1023) >> 2;
        const int q = lin & 3;
        cp16(base + r * RSB + q * 16, g + (size_t)(m0 + r) * K + kk + q * 8);
    }
    // B: 2 tiles (hi/lo) x 128 rows x 4 chunks = 1024 cp ops
#pragma unroll
    for (int j = 0; j < 2; j++) {
        const int lin = tid + j * 512;
        const __nv_bfloat16* g = (lin < 512) ? Bh : Bl;
        const uint32_t base = stage + 2 * A_TILE + ((lin < 512) ? 0u : (uint32_t)B_TILE);
        const int r = (lin & 511) >> 2;
        const int q = lin & 3;
        cp16(base + r * RSB + q * 16, g + (size_t)(n0 + r) * K + kk + q * 8);
    }
    CP_COMMIT();
}

__global__ void __launch_bounds__(512, 1)
gemm_mma3(const __nv_bfloat16* __restrict__ Ah, const __nv_bfloat16* __restrict__ Al,
          const __nv_bfloat16* __restrict__ Bh, const __nv_bfloat16* __restrict__ Bl,
          float* __restrict__ C, int Nn, int K) {
    extern __shared__ char dsm[];
    const uint32_t sb = smem_u32(dsm);
    const int tid  = threadIdx.x;
    const int lane = tid & 31;
    const int wid  = tid >> 5;
    const int wm   = wid & 7;        // 8 warps along M (32 rows each) = 256
    const int wn   = wid >> 3;       // 2 warps along N (64 cols each) = 128
    const int m0   = blockIdx.y * 256;
    const int n0   = blockIdx.x * 128;

    float acc[2][8][4];
#pragma unroll
    for (int mt = 0; mt < 2; mt++)
#pragma unroll
        for (int nt = 0; nt < 8; nt++)
#pragma unroll
            for (int e = 0; e < 4; e++) acc[mt][nt][e] = 0.f;

    const int nkt = K / 32;          // 142
    issue_stage(sb + 0 * STAGE_B, Ah, Al, Bh, Bl, m0, n0, 0,  K, tid);
    issue_stage(sb + 1 * STAGE_B, Ah, Al, Bh, Bl, m0, n0, 32, K, tid);

    int buf = 0;
    for (int kt = 0; kt < nkt; kt++) {
        if (kt + 2 < nkt) {
            int nb = buf + 2; if (nb >= 3) nb -= 3;
            issue_stage(sb + nb * STAGE_B, Ah, Al, Bh, Bl, m0, n0, (kt + 2) * 32, K, tid);
        } else {
            CP_COMMIT();             // empty group keeps wait-count invariant
        }
        CP_WAIT(2);
        __syncthreads();

        const uint32_t stage = sb + buf * STAGE_B;
#pragma unroll
        for (int k16 = 0; k16 < 2; k16++) {
            const uint32_t koff = k16 * 32;   // 16 bf16 = 32 bytes
            uint32_t ah[2][4], al[2][4];
#pragma unroll
            for (int mt = 0; mt < 2; mt++) {
                const uint32_t ra = stage +
                    (uint32_t)((wm * 32 + mt * 16 + (lane & 15)) * RSB + (lane >> 4) * 16) + koff;
                LDSM4(ah[mt], ra);
                LDSM4(al[mt], ra + A_TILE);
            }
            uint32_t bh[4][4], bl[4][4];
#pragma unroll
            for (int p = 0; p < 4; p++) {
                const uint32_t rb = stage + 2 * A_TILE +
                    (uint32_t)((wn * 64 + p * 16 + (lane & 15)) * RSB + (lane >> 4) * 16) + koff;
                LDSM4(bh[p], rb);
                LDSM4(bl[p], rb + B_TILE);
            }
#pragma unroll
            for (int mt = 0; mt < 2; mt++)
#pragma unroll
                for (int nt = 0; nt < 8; nt++) {
                    const int p = nt >> 1, s = nt & 1;
                    MMA_BF16(acc[mt][nt], ah[mt], bh[p][s], bh[p][2 + s]);
                    MMA_BF16(acc[mt][nt], ah[mt], bl[p][s], bl[p][2 + s]);
                    MMA_BF16(acc[mt][nt], al[mt], bh[p][s], bh[p][2 + s]);
                }
        }
        __syncthreads();
        buf++; if (buf == 3) buf = 0;
    }

    // Epilogue: direct fragment stores (float2, 8B aligned since cols are even)
#pragma unroll
    for (int mt = 0; mt < 2; mt++) {
        const int row0 = m0 + wm * 32 + mt * 16 + (lane >> 2);
#pragma unroll
        for (int nt = 0; nt < 8; nt++) {
            const int col = n0 + wn * 64 + nt * 8 + (lane & 3) * 2;
            if (col < Nn) {
                float2 v01; v01.x = acc[mt][nt][0]; v01.y = acc[mt][nt][1];
                float2 v23; v23.x = acc[mt][nt][2]; v23.y = acc[mt][nt][3];
                *(float2*)(C + (size_t)row0 * Nn + col)       = v01;
                *(float2*)(C + (size_t)(row0 + 8) * Nn + col) = v23;
            }
        }
    }
}

// ---------------------------------------------------------------------------
// RoPE + scatter (unchanged)
// ---------------------------------------------------------------------------
__global__ void rope_kernel(const float* __restrict__ fused,
                            float* __restrict__ q, float* __restrict__ k,
                            float* __restrict__ v) {
    const int nl = blockIdx.x;
    const int n  = nl >> 10;
    const int l  = nl & (L_S - 1);
    __shared__ float cs[32], sn[32];
    const int tid = threadIdx.x;
    if (tid < 32) {
        const double f   = pow(10000.0, -(double)tid / 32.0);
        const double ang = (double)l * f;
        cs[tid] = (float)cos(ang);
        sn[tid] = (float)sin(ang);
    }
    __syncthreads();

    const float* src = fused + (size_t)nl * QKV_N;
    for (int idx = tid; idx < (H_Q + 2) * DKV; idx += blockDim.x) {
        const int head = idx >> 6;
        const int d    = idx & 63;
        const float x  = src[idx];
        float out = x;
        if (head < H_Q + 1) {
            const int i = d & 31;
            const float c = cs[i], s = sn[i];
            if (d < 32) out = x * c - src[idx + 32] * s;
            else        out = x * c + src[idx - 32] * s;
        }
        if (head < H_Q)
            q[(((size_t)n * H_Q + head) * L_S + l) * DKV + d] = out;
        else if (head == H_Q)
            k[((size_t)n * L_S + l) * DKV + d] = out;
        else
            v[((size_t)n * L_S + l) * DKV + d] = x;
    }
}

// ---------------------------------------------------------------------------
// Causal MQA flash attention (unchanged, f32x2 math)
// ---------------------------------------------------------------------------
__global__ __launch_bounds__(128, 3)
void attn_kernel(const float* __restrict__ Q, const float* __restrict__ Kb,
                 const float* __restrict__ Vb, float* __restrict__ O) {
    __shared__ float Ks[64][64];
    __shared__ float Vs[64][64];

    const int qt  = (int)gridDim.x - 1 - (int)blockIdx.x;
    const int h   = blockIdx.y;
    const int n   = blockIdx.z;
    const int tid = threadIdx.x;
    const int qi  = qt * 128 + tid;

    const float* qrow = Q + (((size_t)n * H_Q + h) * L_S + qi) * DKV;
    ull q2[32];
    {
        const ulonglong2* qp = (const ulonglong2*)qrow;
#pragma unroll
        for (int t = 0; t < 16; t++) {
            const ulonglong2 w = qp[t];
            q2[2 * t] = w.x; q2[2 * t + 1] = w.y;
        }
    }
    ull o2[32];
#pragma unroll
    for (int d = 0; d < 32; d++) o2[d] = 0ull;
    float mrow = -1e30f, lsum = 0.f;

    const float* Kbase = Kb + (size_t)n * L_S * DKV;
    const float* Vbase = Vb + (size_t)n * L_S * DKV;
    const int ktend = 2 * qt + 1;

    for (int kt = 0; kt <= ktend; kt++) {
        __syncthreads();
#pragma unroll
        for (int p = 0; p < 8; p++) {
            const int lin = tid + p * 128;
            const int r = lin >> 4;
            const int c = (lin & 15) << 2;
            ((float4*)Ks)[lin] = *(const float4*)(Kbase + ((size_t)kt * 64 + r) * DKV + c);
            ((float4*)Vs)[lin] = *(const float4*)(Vbase + ((size_t)kt * 64 + r) * DKV + c);
        }
        __syncthreads();

        const int kbase = kt * 64;
        for (int jc = 0; jc < 8; jc++) {
            float sv[8];
            float cmax = -1e30f;
#pragma unroll
            for (int jj = 0; jj < 8; jj++) {
                const int j = jc * 8 + jj;
                const ulonglong2* krow = (const ulonglong2*)&Ks[j][0];
                ull accA = 0ull, accB = 0ull;
#pragma unroll
                for (int t = 0; t < 16; t++) {
                    const ulonglong2 kk = krow[t];
                    accA = ffma2(q2[2 * t],     kk.x, accA);
                    accB = ffma2(q2[2 * t + 1], kk.y, accB);
                }
                const float2 ra = funpack2(accA);
                const float2 rb = funpack2(accB);
                float s = (ra.x + ra.y + rb.x + rb.y) * 0.125f;
                if (kbase + j > qi) s = -1e30f;
                sv[jj] = s;
                cmax = fmaxf(cmax, s);
            }
            const float newm = fmaxf(mrow, cmax);
            const float corr = __expf(mrow - newm);
            const ull corr2 = fpack2(corr, corr);
#pragma unroll
            for (int d = 0; d < 32; d++) o2[d] = fmul2(o2[d], corr2);
            lsum *= corr;
#pragma unroll
            for (int jj = 0; jj < 8; jj++) {
                const float p = __expf(sv[jj] - newm);
                lsum += p;
                const ull p2 = fpack2(p, p);
                const ulonglong2* vrow = (const ulonglong2*)&Vs[jc * 8 + jj][0];
#pragma unroll
                for (int t = 0; t < 16; t++) {
                    const ulonglong2 vv = vrow[t];
                    o2[2 * t]     = ffma2(vv.x, p2, o2[2 * t]);
                    o2[2 * t + 1] = ffma2(vv.y, p2, o2[2 * t + 1]);
                }
            }
            mrow = newm;
        }
    }

    const float inv = 1.f / lsum;
    const ull inv2 = fpack2(inv, inv);
    float* orow = O + (((size_t)n * L_S + qi) * H_Q + h) * DKV;
#pragma unroll
    for (int d = 0; d < 32; d++) ((ull*)orow)[d] = fmul2(o2[d], inv2);
}

// ---------------------------------------------------------------------------
// launch
// ---------------------------------------------------------------------------
static inline int grid4(long ntotal) { return (int)((ntotal / 4 + 255) / 256); }

extern "C" void kernel_launch(void* const* d_in, const int* in_sizes, int n_in,
                              void* d_out, int out_size) {
    const float* hidden  = (const float*)d_in[0];  // [2,1024,4544]
    const float* w_qkv   = (const float*)d_in[1];  // [4672,4544]
    const float* w_dense = (const float*)d_in[2];  // [4544,4544]
    float* out = (float*)d_out;                    // [2,1024,4544]

    float *fused, *q, *k, *v, *attn;
    __nv_bfloat16 *hid_h, *hid_l, *wq_h, *wq_l, *wd_h, *wd_l, *at_h, *at_l;
    cudaGetSymbolAddress((void**)&fused, g_fused);
    cudaGetSymbolAddress((void**)&q,     g_q);
    cudaGetSymbolAddress((void**)&k,     g_k);
    cudaGetSymbolAddress((void**)&v,     g_v);
    cudaGetSymbolAddress((void**)&attn,  g_attn);
    cudaGetSymbolAddress((void**)&hid_h, g_hid_h);
    cudaGetSymbolAddress((void**)&hid_l, g_hid_l);
    cudaGetSymbolAddress((void**)&wq_h,  g_wq_h);
    cudaGetSymbolAddress((void**)&wq_l,  g_wq_l);
    cudaGetSymbolAddress((void**)&wd_h,  g_wd_h);
    cudaGetSymbolAddress((void**)&wd_l,  g_wd_l);
    cudaGetSymbolAddress((void**)&at_h,  g_at_h);
    cudaGetSymbolAddress((void**)&at_l,  g_at_l);

    cudaFuncSetAttribute(gemm_mma3, cudaFuncAttributeMaxDynamicSharedMemorySize, GSMEM);

    const long n_hid = (long)NL * D_M;
    const long n_wq  = (long)QKV_N * D_M;
    const long n_wqp = (long)QKV_NPAD * D_M;
    const long n_wd  = (long)D_M * D_M;
    const long n_wdp = (long)DM_NPAD * D_M;

    split_bf16<<<grid4(n_hid), 256>>>(hidden,  hid_h, hid_l, n_hid, n_hid);
    split_bf16<<<grid4(n_wqp), 256>>>(w_qkv,   wq_h,  wq_l,  n_wq,  n_wqp);
    split_bf16<<<grid4(n_wdp), 256>>>(w_dense, wd_h,  wd_l,  n_wd,  n_wdp);

    // QKV projection: [2048,4544] x [4672,4544]^T -> fused
    gemm_mma3<<<dim3(QKV_NPAD / 128, NL / 256), 512, GSMEM>>>(
        hid_h, hid_l, wq_h, wq_l, fused, QKV_N, D_M);

    rope_kernel<<<NL, 256>>>(fused, q, k, v);
    attn_kernel<<<dim3(L_S / 128, H_Q, N_B), 128>>>(q, k, v, attn);

    split_bf16<<<grid4(n_hid), 256>>>(attn, at_h, at_l, n_hid, n_hid);

    // Dense projection: [2048,4544] x [4544,4544]^T -> out
    gemm_mma3<<<dim3(DM_NPAD / 128, NL / 256), 512, GSMEM>>>(
        at_h, at_l, wd_h, wd_l, out, D_M, D_M);
}

// round 17
// speedup vs baseline: 1.9775x; 1.0185x over previous
#include <cuda_runtime.h>
#include <cuda_bf16.h>
#include <math.h>
#include <stdint.h>

// Problem constants
#define N_B   2
#define L_S   1024
#define D_M   4544
#define H_Q   71
#define DKV   64
#define NL    (N_B * L_S)          // 2048
#define QKV_N (D_M + 2 * DKV)      // 4672
#define QKV_NPAD 4736              // 37 * 128
#define DM_NPAD  4608              // 36 * 128

typedef unsigned long long ull;

// ---------------------------------------------------------------------------
// packed f32x2 helpers (attention kernel)
// ---------------------------------------------------------------------------
__device__ __forceinline__ ull ffma2(ull a, ull b, ull c) {
    ull d;
    asm("fma.rn.f32x2 %0, %1, %2, %3;" : "=l"(d) : "l"(a), "l"(b), "l"(c));
    return d;
}
__device__ __forceinline__ ull fmul2(ull a, ull b) {
    ull d;
    asm("mul.rn.f32x2 %0, %1, %2;" : "=l"(d) : "l"(a), "l"(b));
    return d;
}
__device__ __forceinline__ ull fpack2(float lo, float hi) {
    ull d;
    asm("mov.b64 %0, {%1, %2};" : "=l"(d) : "f"(lo), "f"(hi));
    return d;
}
__device__ __forceinline__ float2 funpack2(ull v) {
    float2 r;
    asm("mov.b64 {%0, %1}, %2;" : "=f"(r.x), "=f"(r.y) : "l"(v));
    return r;
}

// ---------------------------------------------------------------------------
// mma.sync / ldmatrix / cp.async helpers (portable sm_80+ ISA, works on sm_103)
// ---------------------------------------------------------------------------
__device__ __forceinline__ uint32_t smem_u32(const void* p) {
    uint32_t a;
    asm("{ .reg .u64 t; cvta.to.shared.u64 t, %1; cvt.u32.u64 %0, t; }" : "=r"(a) : "l"(p));
    return a;
}
__device__ __forceinline__ void cp16(uint32_t dst, const void* src) {
    asm volatile("cp.async.cg.shared.global [%0], [%1], 16;" :: "r"(dst), "l"(src) : "memory");
}
#define CP_COMMIT() asm volatile("cp.async.commit_group;" ::: "memory")
#define CP_WAIT(n)  asm volatile("cp.async.wait_group %0;" :: "n"(n) : "memory")

#define LDSM4(r, addr) \
    asm volatile("ldmatrix.sync.aligned.m8n8.x4.shared.b16 {%0,%1,%2,%3}, [%4];" \
        : "=r"((r)[0]), "=r"((r)[1]), "=r"((r)[2]), "=r"((r)[3]) : "r"(addr))

#define MMA_BF16(c, a, b0, b1) \
    asm volatile("mma.sync.aligned.m16n8k16.row.col.f32.bf16.bf16.f32 " \
        "{%0,%1,%2,%3}, {%4,%5,%6,%7}, {%8,%9}, {%0,%1,%2,%3};" \
        : "+f"((c)[0]), "+f"((c)[1]), "+f"((c)[2]), "+f"((c)[3]) \
        : "r"((a)[0]), "r"((a)[1]), "r"((a)[2]), "r"((a)[3]), "r"(b0), "r"(b1))

// ---------------------------------------------------------------------------
// Scratch (no allocation allowed -> __device__ globals)
// ---------------------------------------------------------------------------
__device__ float g_fused[(size_t)NL * QKV_N];
__device__ float g_q[(size_t)N_B * H_Q * L_S * DKV];
__device__ float g_k[(size_t)N_B * L_S * DKV];
__device__ float g_v[(size_t)N_B * L_S * DKV];
// bf16 hi/lo split operands (weights padded with zero rows to a tile multiple)
__device__ __nv_bfloat16 g_hid_h[(size_t)NL * D_M];
__device__ __nv_bfloat16 g_hid_l[(size_t)NL * D_M];
__device__ __nv_bfloat16 g_wq_h[(size_t)QKV_NPAD * D_M];
__device__ __nv_bfloat16 g_wq_l[(size_t)QKV_NPAD * D_M];
__device__ __nv_bfloat16 g_wd_h[(size_t)DM_NPAD * D_M];
__device__ __nv_bfloat16 g_wd_l[(size_t)DM_NPAD * D_M];
__device__ __nv_bfloat16 g_at_h[(size_t)NL * D_M];
__device__ __nv_bfloat16 g_at_l[(size_t)NL * D_M];

// ---------------------------------------------------------------------------
// f32 -> (bf16 hi, bf16 lo) split with zero padding past nvalid.
// ---------------------------------------------------------------------------
__global__ void split_bf16(const float* __restrict__ src, __nv_bfloat16* __restrict__ hi,
                           __nv_bfloat16* __restrict__ lo, long nvalid, long ntotal) {
    const long i4 = ((long)blockIdx.x * blockDim.x + threadIdx.x) * 4;
    if (i4 >= ntotal) return;
    float x[4] = {0.f, 0.f, 0.f, 0.f};
    if (i4 < nvalid) {
        const float4 v = *(const float4*)(src + i4);
        x[0] = v.x; x[1] = v.y; x[2] = v.z; x[3] = v.w;
    }
    __nv_bfloat16 h[4], l[4];
#pragma unroll
    for (int e = 0; e < 4; e++) {
        h[e] = __float2bfloat16(x[e]);
        l[e] = __float2bfloat16(x[e] - __bfloat162float(h[e]));
    }
    __nv_bfloat162* hp = (__nv_bfloat162*)(hi + i4);
    __nv_bfloat162* lp = (__nv_bfloat162*)(lo + i4);
    hp[0] = __nv_bfloat162(h[0], h[1]); hp[1] = __nv_bfloat162(h[2], h[3]);
    lp[0] = __nv_bfloat162(l[0], l[1]); lp[1] = __nv_bfloat162(l[2], l[3]);
}

// ---------------------------------------------------------------------------
// mma.sync bf16 3-pass split GEMM (NT): C[m][n] = sum_k A[m][k]*B[n][k], f32 acc.
// 128x128 CTA tile, BK=32, 256 threads (8 warps of 32x64), 2-stage cp.async.
// __launch_bounds__(256,2) caps regs at 128 so TWO CTAs co-reside per SM:
// independent barrier domains let one CTA's MMAs cover the other's LDSM bursts.
// ---------------------------------------------------------------------------
#define RSB     80                 // bytes per smem row (64 data + 16 pad)
#define TILE_B  (128 * RSB)        // 10240 B per operand tile
#define STAGE_B (4 * TILE_B)       // Ah, Al, Bh, Bl
#define GSMEM   (2 * STAGE_B)      // 81920 B

__device__ __forceinline__ void issue_stage(
    uint32_t stage, const __nv_bfloat16* Ah, const __nv_bfloat16* Al,
    const __nv_bfloat16* Bh, const __nv_bfloat16* Bl,
    int m0, int n0, int kk, int K, int tid) {
#pragma unroll
    for (int a = 0; a < 4; a++) {
        const __nv_bfloat16* g = (a == 0) ? Ah : (a == 1) ? Al : (a == 2) ? Bh : Bl;
        const int r0 = (a < 2) ? m0 : n0;
#pragma unroll
        for (int j = 0; j < 2; j++) {
            const int lin = tid + j * 256;
            const int row = lin >> 2;
            const int q   = lin & 3;
            cp16(stage + a * TILE_B + row * RSB + q * 16,
                 g + (size_t)(r0 + row) * K + kk + q * 8);
        }
    }
    CP_COMMIT();
}

__global__ void __launch_bounds__(256, 2)
gemm_mma3(const __nv_bfloat16* __restrict__ Ah, const __nv_bfloat16* __restrict__ Al,
          const __nv_bfloat16* __restrict__ Bh, const __nv_bfloat16* __restrict__ Bl,
          float* __restrict__ C, int Nn, int K) {
    extern __shared__ char dsm[];
    const uint32_t sb = smem_u32(dsm);
    const int tid  = threadIdx.x;
    const int lane = tid & 31;
    const int wid  = tid >> 5;
    const int wm   = wid & 3;        // 4 warps along M (32 rows each)
    const int wn   = wid >> 2;       // 2 warps along N (64 cols each)
    const int m0   = blockIdx.y * 128;
    const int n0   = blockIdx.x * 128;

    float acc[2][8][4];
#pragma unroll
    for (int mt = 0; mt < 2; mt++)
#pragma unroll
        for (int nt = 0; nt < 8; nt++)
#pragma unroll
            for (int e = 0; e < 4; e++) acc[mt][nt][e] = 0.f;

    const int nkt = K / 32;          // 142
    issue_stage(sb, Ah, Al, Bh, Bl, m0, n0, 0, K, tid);

    for (int kt = 0; kt < nkt; kt++) {
        const uint32_t stage = sb + (kt & 1) * STAGE_B;
        if (kt + 1 < nkt) {
            issue_stage(sb + ((kt + 1) & 1) * STAGE_B, Ah, Al, Bh, Bl,
                        m0, n0, (kt + 1) * 32, K, tid);
            CP_WAIT(1);
        } else {
            CP_WAIT(0);
        }
        __syncthreads();

#pragma unroll
        for (int k16 = 0; k16 < 2; k16++) {
            const uint32_t koff = k16 * 32;   // 16 bf16 = 32 bytes
            uint32_t ah[2][4], al[2][4];
#pragma unroll
            for (int mt = 0; mt < 2; mt++) {
                const uint32_t ra = stage +
                    (uint32_t)((wm * 32 + mt * 16 + (lane & 15)) * RSB + (lane >> 4) * 16) + koff;
                LDSM4(ah[mt], ra);
                LDSM4(al[mt], ra + TILE_B);
            }
            uint32_t bh[4][4], bl[4][4];
#pragma unroll
            for (int p = 0; p < 4; p++) {
                const uint32_t rb = stage + 2 * TILE_B +
                    (uint32_t)((wn * 64 + p * 16 + (lane & 15)) * RSB + (lane >> 4) * 16) + koff;
                LDSM4(bh[p], rb);
                LDSM4(bl[p], rb + TILE_B);
            }
#pragma unroll
            for (int mt = 0; mt < 2; mt++)
#pragma unroll
                for (int nt = 0; nt < 8; nt++) {
                    const int p = nt >> 1, s = nt & 1;
                    MMA_BF16(acc[mt][nt], ah[mt], bh[p][s], bh[p][2 + s]);
                    MMA_BF16(acc[mt][nt], ah[mt], bl[p][s], bl[p][2 + s]);
                    MMA_BF16(acc[mt][nt], al[mt], bh[p][s], bh[p][2 + s]);
                }
        }
        __syncthreads();
    }

    // Epilogue: direct fragment stores (float2, 8B aligned since cols are even)
#pragma unroll
    for (int mt = 0; mt < 2; mt++) {
        const int row0 = m0 + wm * 32 + mt * 16 + (lane >> 2);
#pragma unroll
        for (int nt = 0; nt < 8; nt++) {
            const int col = n0 + wn * 64 + nt * 8 + (lane & 3) * 2;
            if (col < Nn) {
                float2 v01; v01.x = acc[mt][nt][0]; v01.y = acc[mt][nt][1];
                float2 v23; v23.x = acc[mt][nt][2]; v23.y = acc[mt][nt][3];
                *(float2*)(C + (size_t)row0 * Nn + col)       = v01;
                *(float2*)(C + (size_t)(row0 + 8) * Nn + col) = v23;
            }
        }
    }
}

// ---------------------------------------------------------------------------
// RoPE + scatter (unchanged)
// ---------------------------------------------------------------------------
__global__ void rope_kernel(const float* __restrict__ fused,
                            float* __restrict__ q, float* __restrict__ k,
                            float* __restrict__ v) {
    const int nl = blockIdx.x;
    const int n  = nl >> 10;
    const int l  = nl & (L_S - 1);
    __shared__ float cs[32], sn[32];
    const int tid = threadIdx.x;
    if (tid < 32) {
        const double f   = pow(10000.0, -(double)tid / 32.0);
        const double ang = (double)l * f;
        cs[tid] = (float)cos(ang);
        sn[tid] = (float)sin(ang);
    }
    __syncthreads();

    const float* src = fused + (size_t)nl * QKV_N;
    for (int idx = tid; idx < (H_Q + 2) * DKV; idx += blockDim.x) {
        const int head = idx >> 6;
        const int d    = idx & 63;
        const float x  = src[idx];
        float out = x;
        if (head < H_Q + 1) {
            const int i = d & 31;
            const float c = cs[i], s = sn[i];
            if (d < 32) out = x * c - src[idx + 32] * s;
            else        out = x * c + src[idx - 32] * s;
        }
        if (head < H_Q)
            q[(((size_t)n * H_Q + head) * L_S + l) * DKV + d] = out;
        else if (head == H_Q)
            k[((size_t)n * L_S + l) * DKV + d] = out;
        else
            v[((size_t)n * L_S + l) * DKV + d] = x;
    }
}

// ---------------------------------------------------------------------------
// Causal MQA flash attention (f32x2 math). Epilogue now emits the bf16 hi/lo
// split directly (dense-GEMM A operand), deleting a full split pass.
// ---------------------------------------------------------------------------
__global__ __launch_bounds__(128, 3)
void attn_kernel(const float* __restrict__ Q, const float* __restrict__ Kb,
                 const float* __restrict__ Vb,
                 __nv_bfloat16* __restrict__ Oh, __nv_bfloat16* __restrict__ Ol) {
    __shared__ float Ks[64][64];
    __shared__ float Vs[64][64];

    const int qt  = (int)gridDim.x - 1 - (int)blockIdx.x;
    const int h   = blockIdx.y;
    const int n   = blockIdx.z;
    const int tid = threadIdx.x;
    const int qi  = qt * 128 + tid;

    const float* qrow = Q + (((size_t)n * H_Q + h) * L_S + qi) * DKV;
    ull q2[32];
    {
        const ulonglong2* qp = (const ulonglong2*)qrow;
#pragma unroll
        for (int t = 0; t < 16; t++) {
            const ulonglong2 w = qp[t];
            q2[2 * t] = w.x; q2[2 * t + 1] = w.y;
        }
    }
    ull o2[32];
#pragma unroll
    for (int d = 0; d < 32; d++) o2[d] = 0ull;
    float mrow = -1e30f, lsum = 0.f;

    const float* Kbase = Kb + (size_t)n * L_S * DKV;
    const float* Vbase = Vb + (size_t)n * L_S * DKV;
    const int ktend = 2 * qt + 1;

    for (int kt = 0; kt <= ktend; kt++) {
        __syncthreads();
#pragma unroll
        for (int p = 0; p < 8; p++) {
            const int lin = tid + p * 128;
            const int r = lin >> 4;
            const int c = (lin & 15) << 2;
            ((float4*)Ks)[lin] = *(const float4*)(Kbase + ((size_t)kt * 64 + r) * DKV + c);
            ((float4*)Vs)[lin] = *(const float4*)(Vbase + ((size_t)kt * 64 + r) * DKV + c);
        }
        __syncthreads();

        const int kbase = kt * 64;
        for (int jc = 0; jc < 8; jc++) {
            float sv[8];
            float cmax = -1e30f;
#pragma unroll
            for (int jj = 0; jj < 8; jj++) {
                const int j = jc * 8 + jj;
                const ulonglong2* krow = (const ulonglong2*)&Ks[j][0];
                ull accA = 0ull, accB = 0ull;
#pragma unroll
                for (int t = 0; t < 16; t++) {
                    const ulonglong2 kk = krow[t];
                    accA = ffma2(q2[2 * t],     kk.x, accA);
                    accB = ffma2(q2[2 * t + 1], kk.y, accB);
                }
                const float2 ra = funpack2(accA);
                const float2 rb = funpack2(accB);
                float s = (ra.x + ra.y + rb.x + rb.y) * 0.125f;
                if (kbase + j > qi) s = -1e30f;
                sv[jj] = s;
                cmax = fmaxf(cmax, s);
            }
            const float newm = fmaxf(mrow, cmax);
            const float corr = __expf(mrow - newm);
            const ull corr2 = fpack2(corr, corr);
#pragma unroll
            for (int d = 0; d < 32; d++) o2[d] = fmul2(o2[d], corr2);
            lsum *= corr;
#pragma unroll
            for (int jj = 0; jj < 8; jj++) {
                const float p = __expf(sv[jj] - newm);
                lsum += p;
                const ull p2 = fpack2(p, p);
                const ulonglong2* vrow = (const ulonglong2*)&Vs[jc * 8 + jj][0];
#pragma unroll
                for (int t = 0; t < 16; t++) {
                    const ulonglong2 vv = vrow[t];
                    o2[2 * t]     = ffma2(vv.x, p2, o2[2 * t]);
                    o2[2 * t + 1] = ffma2(vv.y, p2, o2[2 * t + 1]);
                }
            }
            mrow = newm;
        }
    }

    const float inv = 1.f / lsum;
    const ull inv2 = fpack2(inv, inv);
    const size_t obase = ((size_t)n * L_S + qi) * D_M + h * DKV;
#pragma unroll
    for (int d = 0; d < 32; d++) {
        const float2 v = funpack2(fmul2(o2[d], inv2));
        const __nv_bfloat16 h0 = __float2bfloat16(v.x);
        const __nv_bfloat16 h1 = __float2bfloat16(v.y);
        const __nv_bfloat16 l0 = __float2bfloat16(v.x - __bfloat162float(h0));
        const __nv_bfloat16 l1 = __float2bfloat16(v.y - __bfloat162float(h1));
        *(__nv_bfloat162*)(Oh + obase + 2 * d) = __nv_bfloat162(h0, h1);
        *(__nv_bfloat162*)(Ol + obase + 2 * d) = __nv_bfloat162(l0, l1);
    }
}

// ---------------------------------------------------------------------------
// launch
// ---------------------------------------------------------------------------
static inline int grid4(long ntotal) { return (int)((ntotal / 4 + 255) / 256); }

extern "C" void kernel_launch(void* const* d_in, const int* in_sizes, int n_in,
                              void* d_out, int out_size) {
    const float* hidden  = (const float*)d_in[0];  // [2,1024,4544]
    const float* w_qkv   = (const float*)d_in[1];  // [4672,4544]
    const float* w_dense = (const float*)d_in[2];  // [4544,4544]
    float* out = (float*)d_out;                    // [2,1024,4544]

    float *fused, *q, *k, *v;
    __nv_bfloat16 *hid_h, *hid_l, *wq_h, *wq_l, *wd_h, *wd_l, *at_h, *at_l;
    cudaGetSymbolAddress((void**)&fused, g_fused);
    cudaGetSymbolAddress((void**)&q,     g_q);
    cudaGetSymbolAddress((void**)&k,     g_k);
    cudaGetSymbolAddress((void**)&v,     g_v);
    cudaGetSymbolAddress((void**)&hid_h, g_hid_h);
    cudaGetSymbolAddress((void**)&hid_l, g_hid_l);
    cudaGetSymbolAddress((void**)&wq_h,  g_wq_h);
    cudaGetSymbolAddress((void**)&wq_l,  g_wq_l);
    cudaGetSymbolAddress((void**)&wd_h,  g_wd_h);
    cudaGetSymbolAddress((void**)&wd_l,  g_wd_l);
    cudaGetSymbolAddress((void**)&at_h,  g_at_h);
    cudaGetSymbolAddress((void**)&at_l,  g_at_l);

    cudaFuncSetAttribute(gemm_mma3, cudaFuncAttributeMaxDynamicSharedMemorySize, GSMEM);

    const long n_hid = (long)NL * D_M;
    const long n_wq  = (long)QKV_N * D_M;
    const long n_wqp = (long)QKV_NPAD * D_M;
    const long n_wd  = (long)D_M * D_M;
    const long n_wdp = (long)DM_NPAD * D_M;

    split_bf16<<<grid4(n_hid), 256>>>(hidden,  hid_h, hid_l, n_hid, n_hid);
    split_bf16<<<grid4(n_wqp), 256>>>(w_qkv,   wq_h,  wq_l,  n_wq,  n_wqp);
    split_bf16<<<grid4(n_wdp), 256>>>(w_dense, wd_h,  wd_l,  n_wd,  n_wdp);

    // QKV projection: [2048,4544] x [4672,4544]^T -> fused
    gemm_mma3<<<dim3(QKV_NPAD / 128, NL / 128), 256, GSMEM>>>(
        hid_h, hid_l, wq_h, wq_l, fused, QKV_N, D_M);

    rope_kernel<<<NL, 256>>>(fused, q, k, v);
    attn_kernel<<<dim3(L_S / 128, H_Q, N_B), 128>>>(q, k, v, at_h, at_l);

    // Dense projection: [2048,4544] x [4544,4544]^T -> out
    gemm_mma3<<<dim3(DM_NPAD / 128, NL / 128), 256, GSMEM>>>(
        at_h, at_l, wd_h, wd_l, out, D_M, D_M);
}